// round 8
// baseline (speedup 1.0000x reference)
#include <cuda_runtime.h>
#include <math.h>

#define SEQ   1000
#define HID   100
#define IND   8
#define BATCH 128
#define NOUT  2
#define B_J0  0.01f
#define BETA  1.8f

#define NTH 256
#define SMEM_FLOATS (3*HID*HID + HID*NOUT)   // Wrec1, Wrec2, Win2, roW half
#define SMEM_BYTES  (SMEM_FLOATS * 4)

struct Params { const float* in[24]; };

// partial readout accumulators: [dir][batch][out]
__device__ float g_partial[2][BATCH][NOUT];

// XLA:CPU vectorized f32 exp (Cephes / GenerateVF32Exp). Bit-identical to
// correctly-rounded exp on this problem's input range (verified R5==R6).
__device__ __forceinline__ float xla_expf(float x)
{
    const float exp_hi = 88.3762626647950f;
    const float exp_lo = -88.3762626647949f;
    const float LOG2EF = 1.44269504088896341f;
    const float C1 = 0.693359375f;
    const float C2 = -2.12194440e-4f;
    const float p0 = 1.9875691500E-4f;
    const float p1 = 1.3981999507E-3f;
    const float p2 = 8.3334519073E-3f;
    const float p3 = 4.1665795894E-2f;
    const float p4 = 1.6666665459E-1f;
    const float p5 = 5.0000001201E-1f;

    float xc  = fminf(fmaxf(x, exp_lo), exp_hi);
    float fx  = floorf(__fmaf_rn(xc, LOG2EF, 0.5f));
    float tmp = __fmul_rn(C1, fx);
    float z   = __fmul_rn(C2, fx);
    float r   = __fsub_rn(xc, tmp);
    r = __fsub_rn(r, z);
    z = __fmul_rn(r, r);
    float y = __fmaf_rn(r, p0, p1);
    y = __fmaf_rn(y, r, p2);
    y = __fmaf_rn(y, r, p3);
    y = __fmaf_rn(y, r, p4);
    y = __fmaf_rn(y, r, p5);
    y = __fmaf_rn(y, z, r);
    y = __fadd_rn(y, 1.0f);
    int n = (int)fx;
    float s = __uint_as_float((unsigned)(n + 127) << 23);
    return fmaxf(__fmul_rn(y, s), x);
}

__global__ void __launch_bounds__(NTH, 1)
srnn_kernel(Params prm)
{
    extern __shared__ float sm[];
    float* sW1 = sm;                    // layer1 Wrec  [100][100]
    float* sW2 = sm + HID*HID;          // layer2 Wrec  [100][100]
    float* sI2 = sm + 2*HID*HID;        // layer2 Win   [100][100]
    float* sRo = sm + 3*HID*HID;        // ro_W half    [100][2]
    __shared__ unsigned sBall[2][2][2][4]; // [row_in_blk][layer][parity][word]

    const int tid  = threadIdx.x;
    const int dir  = blockIdx.x & 1;          // 0 = forward, 1 = backward
    const int rowb = tid >> 7;                // 0 or 1 (two batch rows per block)
    const int h    = tid & 127;               // neuron index (valid < 100)
    const int row  = (blockIdx.x >> 1) * 2 + rowb;
    const bool act = (h < HID);

    const float* inp = prm.in[0];
    const int b1i = dir ? 6 : 1;    // layer1 param base (fw1 / bw1)
    const int b2i = dir ? 16 : 11;  // layer2 param base (fw2 / bw2)
    const float* Win1  = prm.in[b1i + 0];
    const float* b1v   = prm.in[b1i + 1];
    const float* Wr1   = prm.in[b1i + 2];
    const float* tm1   = prm.in[b1i + 3];
    const float* ta1   = prm.in[b1i + 4];
    const float* Win2g = prm.in[b2i + 0];
    const float* b2v   = prm.in[b2i + 1];
    const float* Wr2   = prm.in[b2i + 2];
    const float* tm2   = prm.in[b2i + 3];
    const float* ta2   = prm.in[b2i + 4];
    const float* roW   = prm.in[21] + dir * (HID * NOUT);
    const float* rob   = prm.in[22];
    const float* rotau = prm.in[23];

    // ---- stage weights to SMEM ----
    for (int i = tid; i < HID*HID; i += NTH) {
        sW1[i] = Wr1[i];
        sW2[i] = Wr2[i];
        sI2[i] = Win2g[i];
    }
    for (int i = tid; i < HID*NOUT; i += NTH) sRo[i] = roW[i];
    if (tid < 32) ((unsigned*)sBall)[tid] = 0u;

    // ---- per-thread constants / state ----
    float w_in[IND];
    float bias1 = 0.f, bias2 = 0.f;
    float a1 = 0.f, om1 = 0.f, r1 = 0.f, or1 = 0.f;
    float a2 = 0.f, om2 = 0.f, r2 = 0.f, or2 = 0.f;
    if (act) {
        #pragma unroll
        for (int d = 0; d < IND; d++) w_in[d] = Win1[d*HID + h];
        bias1 = b1v[h]; bias2 = b2v[h];
        a1 = xla_expf(__fdiv_rn(-1.0f, tm1[h])); om1 = __fsub_rn(1.0f, a1);
        r1 = xla_expf(__fdiv_rn(-1.0f, ta1[h])); or1 = __fsub_rn(1.0f, r1);
        a2 = xla_expf(__fdiv_rn(-1.0f, tm2[h])); om2 = __fsub_rn(1.0f, a2);
        r2 = xla_expf(__fdiv_rn(-1.0f, ta2[h])); or2 = __fsub_rn(1.0f, r2);
    }
    float mem1 = 0.f, bb1 = B_J0, s1 = 0.f;
    float mem2 = 0.f, bb2 = B_J0, s2 = 0.f;

    // readout state (owned by h==0 of each row)
    float aro0 = 0.f, aro1 = 0.f, oro0 = 0.f, oro1 = 0.f;
    float mro0 = 0.f, mro1 = 0.f, rb0 = 0.f, rb1 = 0.f;
    if (h == 0) {
        aro0 = xla_expf(__fdiv_rn(-1.0f, rotau[0])); oro0 = __fsub_rn(1.0f, aro0);
        aro1 = xla_expf(__fdiv_rn(-1.0f, rotau[1])); oro1 = __fsub_rn(1.0f, aro1);
        if (dir == 0) { rb0 = rob[0]; rb1 = rob[1]; }  // ro_b counted exactly once
    }

    const float* xrow = inp + (size_t)row * SEQ * IND;

    __syncthreads();

    // prefetch x for t = 0
    float xn[IND];
    if (act) {
        const int te = dir ? (SEQ - 1) : 0;
        #pragma unroll
        for (int d = 0; d < IND; d++) xn[d] = __ldg(xrow + te*IND + d);
    }

    for (int t = 0; t < SEQ; t++) {
        const int wp = t & 1, rp = wp ^ 1;

        float xc[IND];
        if (act) {
            #pragma unroll
            for (int d = 0; d < IND; d++) xc[d] = xn[d];
            if (t + 1 < SEQ) {  // prefetch next step's input
                const int te = dir ? (SEQ - 2 - t) : (t + 1);
                #pragma unroll
                for (int d = 0; d < IND; d++) xn[d] = __ldg(xrow + te*IND + d);
            }
        }

        // previous-step spike ballots
        unsigned B1[4], B2[4];
        #pragma unroll
        for (int w = 0; w < 4; w++) {
            B1[w] = sBall[rowb][0][rp][w];
            B2[w] = sBall[rowb][1][rp][w];
        }

        // readout of step t-1 (layer2 ballots from t-1), folded into this step
        if (h == 0 && t > 0) {
            float y0 = 0.f, y1 = 0.f;
            #pragma unroll
            for (int w = 0; w < 4; w++) {
                unsigned m = B2[w];
                while (m) {
                    int j = w*32 + __ffs(m) - 1;
                    m &= m - 1;
                    y0 = __fadd_rn(y0, sRo[j*NOUT + 0]);
                    y1 = __fadd_rn(y1, sRo[j*NOUT + 1]);
                }
            }
            y0 = __fadd_rn(y0, rb0);
            y1 = __fadd_rn(y1, rb1);
            mro0 = __fmaf_rn(aro0, mro0, __fmul_rn(oro0, y0));
            mro1 = __fmaf_rn(aro1, mro1, __fmul_rn(oro1, y1));
        }

        // recurrent gathers (t-1 spikes; ascending j == Eigen serial-k order;
        // for 0/1 operands fadd == fma accumulation, bit-exact)
        float rec1 = 0.f, rec2 = 0.f;
        if (act) {
            #pragma unroll
            for (int w = 0; w < 4; w++) {
                const float* p = sW1 + w*32*HID + h;
                unsigned m = B1[w];
                while (m) { int b = __ffs(m) - 1; m &= m - 1; rec1 = __fadd_rn(rec1, p[b*HID]); }
            }
            #pragma unroll
            for (int w = 0; w < 4; w++) {
                const float* p = sW2 + w*32*HID + h;
                unsigned m = B2[w];
                while (m) { int b = __ffs(m) - 1; m &= m - 1; rec2 = __fadd_rn(rec2, p[b*HID]); }
            }
        }

        // ---- layer1 update ----
        bool pred1 = false;
        if (act) {
            // K=8 input dot, LLVM loop-vectorized shape (VF=4, 2 iters):
            // lane acc_d = fma(x[4+d], w[4+d], x[d]*w[d]);
            // horizontal faddp tree: (acc0+acc1) + (acc2+acc3)
            float A0 = __fmaf_rn(xc[4], w_in[4], __fmul_rn(xc[0], w_in[0]));
            float A1 = __fmaf_rn(xc[5], w_in[5], __fmul_rn(xc[1], w_in[1]));
            float A2 = __fmaf_rn(xc[6], w_in[6], __fmul_rn(xc[2], w_in[2]));
            float A3 = __fmaf_rn(xc[7], w_in[7], __fmul_rn(xc[3], w_in[3]));
            float in1 = __fadd_rn(__fadd_rn(A0, A1), __fadd_rn(A2, A3));

            float cur = __fadd_rn(__fadd_rn(in1, bias1), rec1);
            // fast-math-contracted elementwise shapes (R4, best so far)
            bb1 = __fmaf_rn(r1, bb1, __fmul_rn(or1, s1));
            float thr = __fmaf_rn(BETA, bb1, B_J0);
            mem1 = __fmaf_rn(a1, mem1, __fmul_rn(om1, cur));
            mem1 = __fmaf_rn(-thr, s1, mem1);
            pred1 = __fsub_rn(mem1, thr) > 0.f;
            s1 = pred1 ? 1.f : 0.f;
        }
        unsigned bal1 = __ballot_sync(0xffffffffu, pred1);
        if ((tid & 31) == 0) sBall[rowb][0][wp][(tid >> 5) & 3] = bal1;
        __syncthreads();

        // ---- layer2 update (input = layer1 spikes of THIS step) ----
        bool pred2 = false;
        if (act) {
            float in2 = 0.f;
            #pragma unroll
            for (int w = 0; w < 4; w++) {
                const float* p = sI2 + w*32*HID + h;
                unsigned m = sBall[rowb][0][wp][w];
                while (m) { int b = __ffs(m) - 1; m &= m - 1; in2 = __fadd_rn(in2, p[b*HID]); }
            }
            float cur = __fadd_rn(__fadd_rn(in2, bias2), rec2);
            bb2 = __fmaf_rn(r2, bb2, __fmul_rn(or2, s2));
            float thr = __fmaf_rn(BETA, bb2, B_J0);
            mem2 = __fmaf_rn(a2, mem2, __fmul_rn(om2, cur));
            mem2 = __fmaf_rn(-thr, s2, mem2);
            pred2 = __fsub_rn(mem2, thr) > 0.f;
            s2 = pred2 ? 1.f : 0.f;
        }
        unsigned bal2 = __ballot_sync(0xffffffffu, pred2);
        if ((tid & 31) == 0) sBall[rowb][1][wp][(tid >> 5) & 3] = bal2;
        __syncthreads();
    }

    // final readout step (s = SEQ-1)
    if (h == 0) {
        const int rp = (SEQ - 1) & 1;
        float y0 = 0.f, y1 = 0.f;
        #pragma unroll
        for (int w = 0; w < 4; w++) {
            unsigned m = sBall[rowb][1][rp][w];
            while (m) {
                int j = w*32 + __ffs(m) - 1;
                m &= m - 1;
                y0 = __fadd_rn(y0, sRo[j*NOUT + 0]);
                y1 = __fadd_rn(y1, sRo[j*NOUT + 1]);
            }
        }
        y0 = __fadd_rn(y0, rb0);
        y1 = __fadd_rn(y1, rb1);
        mro0 = __fmaf_rn(aro0, mro0, __fmul_rn(oro0, y0));
        mro1 = __fmaf_rn(aro1, mro1, __fmul_rn(oro1, y1));
        g_partial[dir][row][0] = mro0;
        g_partial[dir][row][1] = mro1;
    }
}

__global__ void fin_kernel(float* __restrict__ out)
{
    const int b = threadIdx.x;
    float v0 = __fadd_rn(g_partial[0][b][0], g_partial[1][b][0]);
    float v1 = __fadd_rn(g_partial[0][b][1], g_partial[1][b][1]);
    // jax.nn.log_softmax: shifted = x - max; out = shifted - log(sum(exp(shifted)))
    float mx = fmaxf(v0, v1);
    float sh0 = __fsub_rn(v0, mx);
    float sh1 = __fsub_rn(v1, mx);
    float e0 = (float)exp((double)sh0);
    float e1 = (float)exp((double)sh1);
    float lse = (float)log((double)__fadd_rn(e0, e1));
    out[2*b + 0] = __fsub_rn(sh0, lse);
    out[2*b + 1] = __fsub_rn(sh1, lse);
}

extern "C" void kernel_launch(void* const* d_in, const int* in_sizes, int n_in,
                              void* d_out, int out_size)
{
    (void)in_sizes; (void)n_in; (void)out_size;
    Params prm;
    for (int i = 0; i < 24; i++) prm.in[i] = (const float*)d_in[i];

    cudaFuncSetAttribute(srnn_kernel,
                         cudaFuncAttributeMaxDynamicSharedMemorySize, SMEM_BYTES);
    srnn_kernel<<<BATCH, NTH, SMEM_BYTES>>>(prm);
    fin_kernel<<<1, BATCH>>>((float*)d_out);
}

// round 9
// speedup vs baseline: 1.1667x; 1.1667x over previous
#include <cuda_runtime.h>
#include <math.h>

#define SEQ   1000
#define HID   100
#define IND   8
#define BATCH 128
#define NOUT  2
#define B_J0  0.01f
#define BETA  1.8f

#define NTH 64   // 2 warps per block, one batch row per warp
#define SMEM_FLOATS (3*HID*HID + HID*NOUT)   // Wrec1, Wrec2, Win2, roW half
#define SMEM_BYTES  (SMEM_FLOATS * 4)

struct Params { const float* in[24]; };

// partial readout accumulators: [dir][batch][out]
__device__ float g_partial[2][BATCH][NOUT];

// XLA:CPU vectorized f32 exp (Cephes / GenerateVF32Exp). Matches reference
// bit-for-bit on this problem's input range (established R5/R6/R8).
__device__ __forceinline__ float xla_expf(float x)
{
    const float exp_hi = 88.3762626647950f;
    const float exp_lo = -88.3762626647949f;
    const float LOG2EF = 1.44269504088896341f;
    const float C1 = 0.693359375f;
    const float C2 = -2.12194440e-4f;
    const float p0 = 1.9875691500E-4f;
    const float p1 = 1.3981999507E-3f;
    const float p2 = 8.3334519073E-3f;
    const float p3 = 4.1665795894E-2f;
    const float p4 = 1.6666665459E-1f;
    const float p5 = 5.0000001201E-1f;

    float xc  = fminf(fmaxf(x, exp_lo), exp_hi);
    float fx  = floorf(__fmaf_rn(xc, LOG2EF, 0.5f));
    float tmp = __fmul_rn(C1, fx);
    float z   = __fmul_rn(C2, fx);
    float r   = __fsub_rn(xc, tmp);
    r = __fsub_rn(r, z);
    z = __fmul_rn(r, r);
    float y = __fmaf_rn(r, p0, p1);
    y = __fmaf_rn(y, r, p2);
    y = __fmaf_rn(y, r, p3);
    y = __fmaf_rn(y, r, p4);
    y = __fmaf_rn(y, r, p5);
    y = __fmaf_rn(y, z, r);
    y = __fadd_rn(y, 1.0f);
    int n = (int)fx;
    float s = __uint_as_float((unsigned)(n + 127) << 23);
    return fmaxf(__fmul_rn(y, s), x);
}

__global__ void __launch_bounds__(NTH, 1)
srnn_kernel(Params prm)
{
    extern __shared__ float sm[];
    float* sW1 = sm;                    // layer1 Wrec  [100][100]
    float* sW2 = sm + HID*HID;          // layer2 Wrec  [100][100]
    float* sI2 = sm + 2*HID*HID;        // layer2 Win   [100][100]
    float* sRo = sm + 3*HID*HID;        // ro_W half    [100][2]

    const int tid  = threadIdx.x;
    const int lane = tid & 31;
    const int wid  = tid >> 5;                // warp in block = row select
    const int dir  = blockIdx.x & 1;          // 0 = forward, 1 = backward
    const int row  = (blockIdx.x >> 1) * 2 + wid;

    const float* inp = prm.in[0];
    const int b1i = dir ? 6 : 1;    // layer1 param base (fw1 / bw1)
    const int b2i = dir ? 16 : 11;  // layer2 param base (fw2 / bw2)
    const float* Win1  = prm.in[b1i + 0];
    const float* b1v   = prm.in[b1i + 1];
    const float* Wr1   = prm.in[b1i + 2];
    const float* tm1   = prm.in[b1i + 3];
    const float* ta1   = prm.in[b1i + 4];
    const float* Win2g = prm.in[b2i + 0];
    const float* b2vv  = prm.in[b2i + 1];
    const float* Wr2   = prm.in[b2i + 2];
    const float* tm2   = prm.in[b2i + 3];
    const float* ta2   = prm.in[b2i + 4];
    const float* roW   = prm.in[21] + dir * (HID * NOUT);
    const float* rob   = prm.in[22];
    const float* rotau = prm.in[23];

    // ---- stage weights to SMEM (both warps cooperate) ----
    for (int i = tid; i < HID*HID; i += NTH) {
        sW1[i] = Wr1[i];
        sW2[i] = Wr2[i];
        sI2[i] = Win2g[i];
    }
    for (int i = tid; i < HID*NOUT; i += NTH) sRo[i] = roW[i];

    // ---- per-thread constants / state (4 neuron slots: lane + 32*s) ----
    // slot 3 valid only for lane < 4; invalid slots use a safe index and are
    // masked out of ballots.
    const bool v3 = (lane < 4);
    int hs[4];
    hs[0] = lane; hs[1] = lane + 32; hs[2] = lane + 64; hs[3] = v3 ? lane + 96 : 0;
    const int off3 = v3 ? 96 : 0;   // safe smem gather offset for slot 3

    float w_in[4][IND];
    float bias1[4], bias2[4];
    float a1[4], om1[4], r1[4], or1[4], a2[4], om2[4], r2[4], or2[4];
    #pragma unroll
    for (int s = 0; s < 4; s++) {
        int h = hs[s];
        #pragma unroll
        for (int d = 0; d < IND; d++) w_in[s][d] = Win1[d*HID + h];
        bias1[s] = b1v[h]; bias2[s] = b2vv[h];
        a1[s] = xla_expf(__fdiv_rn(-1.0f, tm1[h])); om1[s] = __fsub_rn(1.0f, a1[s]);
        r1[s] = xla_expf(__fdiv_rn(-1.0f, ta1[h])); or1[s] = __fsub_rn(1.0f, r1[s]);
        a2[s] = xla_expf(__fdiv_rn(-1.0f, tm2[h])); om2[s] = __fsub_rn(1.0f, a2[s]);
        r2[s] = xla_expf(__fdiv_rn(-1.0f, ta2[h])); or2[s] = __fsub_rn(1.0f, r2[s]);
    }
    float mem1[4] = {0.f,0.f,0.f,0.f}, bb1[4] = {B_J0,B_J0,B_J0,B_J0}, s1[4] = {0.f,0.f,0.f,0.f};
    float mem2[4] = {0.f,0.f,0.f,0.f}, bb2[4] = {B_J0,B_J0,B_J0,B_J0}, s2[4] = {0.f,0.f,0.f,0.f};

    // readout state (lane 0 of each warp)
    float aro0 = 0.f, aro1 = 0.f, oro0 = 0.f, oro1 = 0.f;
    float mro0 = 0.f, mro1 = 0.f, rb0 = 0.f, rb1 = 0.f;
    if (lane == 0) {
        aro0 = xla_expf(__fdiv_rn(-1.0f, rotau[0])); oro0 = __fsub_rn(1.0f, aro0);
        aro1 = xla_expf(__fdiv_rn(-1.0f, rotau[1])); oro1 = __fsub_rn(1.0f, aro1);
        if (dir == 0) { rb0 = rob[0]; rb1 = rob[1]; }  // ro_b counted exactly once
    }

    const float* xrow = inp + (size_t)row * SEQ * IND;

    __syncthreads();   // weights staged (one-time)

    unsigned B1[4] = {0u,0u,0u,0u};   // layer1 spikes, previous step
    unsigned B2[4] = {0u,0u,0u,0u};   // layer2 spikes, previous step

    // prefetch x for t = 0
    float xn[IND];
    {
        const int te = dir ? (SEQ - 1) : 0;
        #pragma unroll
        for (int d = 0; d < IND; d++) xn[d] = __ldg(xrow + te*IND + d);
    }

    for (int t = 0; t < SEQ; t++) {
        float xc[IND];
        #pragma unroll
        for (int d = 0; d < IND; d++) xc[d] = xn[d];
        if (t + 1 < SEQ) {  // prefetch next step's input
            const int te = dir ? (SEQ - 2 - t) : (t + 1);
            #pragma unroll
            for (int d = 0; d < IND; d++) xn[d] = __ldg(xrow + te*IND + d);
        }

        // readout of step t-1 (layer2 spikes of t-1), folded into this step
        if (lane == 0 && t > 0) {
            float y0 = 0.f, y1 = 0.f;
            #pragma unroll
            for (int w = 0; w < 4; w++) {
                unsigned m = B2[w];
                while (m) {
                    int j = w*32 + __ffs(m) - 1;
                    m &= m - 1;
                    y0 = __fadd_rn(y0, sRo[j*NOUT + 0]);
                    y1 = __fadd_rn(y1, sRo[j*NOUT + 1]);
                }
            }
            y0 = __fadd_rn(y0, rb0);
            y1 = __fadd_rn(y1, rb1);
            mro0 = __fmaf_rn(aro0, mro0, __fmul_rn(oro0, y0));
            mro1 = __fmaf_rn(aro1, mro1, __fmul_rn(oro1, y1));
        }

        // recurrent gathers from previous-step spikes (ascending j; per-slot
        // independent accumulators preserve reference serial-k order)
        float rec1[4] = {0.f,0.f,0.f,0.f};
        float rec2[4] = {0.f,0.f,0.f,0.f};
        #pragma unroll
        for (int w = 0; w < 4; w++) {
            unsigned m = B1[w];
            const float* base = sW1 + w*32*HID + lane;
            while (m) {
                int b = __ffs(m) - 1; m &= m - 1;
                const float* p = base + b*HID;
                rec1[0] = __fadd_rn(rec1[0], p[0]);
                rec1[1] = __fadd_rn(rec1[1], p[32]);
                rec1[2] = __fadd_rn(rec1[2], p[64]);
                rec1[3] = __fadd_rn(rec1[3], p[off3]);
            }
        }
        #pragma unroll
        for (int w = 0; w < 4; w++) {
            unsigned m = B2[w];
            const float* base = sW2 + w*32*HID + lane;
            while (m) {
                int b = __ffs(m) - 1; m &= m - 1;
                const float* p = base + b*HID;
                rec2[0] = __fadd_rn(rec2[0], p[0]);
                rec2[1] = __fadd_rn(rec2[1], p[32]);
                rec2[2] = __fadd_rn(rec2[2], p[64]);
                rec2[3] = __fadd_rn(rec2[3], p[off3]);
            }
        }

        // ---- layer1 update (4 slots) ----
        bool pr1[4];
        #pragma unroll
        for (int s = 0; s < 4; s++) {
            // K=8 input dot, LLVM VF=4 shape: acc_d = fma(x[4+d],w[4+d],x[d]*w[d]);
            // horizontal pairwise: (A0+A1) + (A2+A3)
            float A0 = __fmaf_rn(xc[4], w_in[s][4], __fmul_rn(xc[0], w_in[s][0]));
            float A1 = __fmaf_rn(xc[5], w_in[s][5], __fmul_rn(xc[1], w_in[s][1]));
            float A2 = __fmaf_rn(xc[6], w_in[s][6], __fmul_rn(xc[2], w_in[s][2]));
            float A3 = __fmaf_rn(xc[7], w_in[s][7], __fmul_rn(xc[3], w_in[s][3]));
            float in1 = __fadd_rn(__fadd_rn(A0, A1), __fadd_rn(A2, A3));

            float cur = __fadd_rn(__fadd_rn(in1, bias1[s]), rec1[s]);
            bb1[s] = __fmaf_rn(r1[s], bb1[s], __fmul_rn(or1[s], s1[s]));
            float thr = __fmaf_rn(BETA, bb1[s], B_J0);
            mem1[s] = __fmaf_rn(a1[s], mem1[s], __fmul_rn(om1[s], cur));
            mem1[s] = __fmaf_rn(-thr, s1[s], mem1[s]);
            pr1[s] = __fsub_rn(mem1[s], thr) > 0.f;
            s1[s] = pr1[s] ? 1.f : 0.f;
        }
        // slot 3 invalid lanes must not spike
        if (!v3) { pr1[3] = false; s1[3] = 0.f; }
        unsigned NB1[4];
        NB1[0] = __ballot_sync(0xffffffffu, pr1[0]);
        NB1[1] = __ballot_sync(0xffffffffu, pr1[1]);
        NB1[2] = __ballot_sync(0xffffffffu, pr1[2]);
        NB1[3] = __ballot_sync(0xffffffffu, pr1[3]);

        // ---- layer2 input gather (THIS step's layer1 spikes) ----
        float in2[4] = {0.f,0.f,0.f,0.f};
        #pragma unroll
        for (int w = 0; w < 4; w++) {
            unsigned m = NB1[w];
            const float* base = sI2 + w*32*HID + lane;
            while (m) {
                int b = __ffs(m) - 1; m &= m - 1;
                const float* p = base + b*HID;
                in2[0] = __fadd_rn(in2[0], p[0]);
                in2[1] = __fadd_rn(in2[1], p[32]);
                in2[2] = __fadd_rn(in2[2], p[64]);
                in2[3] = __fadd_rn(in2[3], p[off3]);
            }
        }

        // ---- layer2 update (4 slots) ----
        bool pr2[4];
        #pragma unroll
        for (int s = 0; s < 4; s++) {
            float cur = __fadd_rn(__fadd_rn(in2[s], bias2[s]), rec2[s]);
            bb2[s] = __fmaf_rn(r2[s], bb2[s], __fmul_rn(or2[s], s2[s]));
            float thr = __fmaf_rn(BETA, bb2[s], B_J0);
            mem2[s] = __fmaf_rn(a2[s], mem2[s], __fmul_rn(om2[s], cur));
            mem2[s] = __fmaf_rn(-thr, s2[s], mem2[s]);
            pr2[s] = __fsub_rn(mem2[s], thr) > 0.f;
            s2[s] = pr2[s] ? 1.f : 0.f;
        }
        if (!v3) { pr2[3] = false; s2[3] = 0.f; }
        unsigned NB2[4];
        NB2[0] = __ballot_sync(0xffffffffu, pr2[0]);
        NB2[1] = __ballot_sync(0xffffffffu, pr2[1]);
        NB2[2] = __ballot_sync(0xffffffffu, pr2[2]);
        NB2[3] = __ballot_sync(0xffffffffu, pr2[3]);

        #pragma unroll
        for (int w = 0; w < 4; w++) { B1[w] = NB1[w]; B2[w] = NB2[w]; }
    }

    // final readout step (s = SEQ-1)
    if (lane == 0) {
        float y0 = 0.f, y1 = 0.f;
        #pragma unroll
        for (int w = 0; w < 4; w++) {
            unsigned m = B2[w];
            while (m) {
                int j = w*32 + __ffs(m) - 1;
                m &= m - 1;
                y0 = __fadd_rn(y0, sRo[j*NOUT + 0]);
                y1 = __fadd_rn(y1, sRo[j*NOUT + 1]);
            }
        }
        y0 = __fadd_rn(y0, rb0);
        y1 = __fadd_rn(y1, rb1);
        mro0 = __fmaf_rn(aro0, mro0, __fmul_rn(oro0, y0));
        mro1 = __fmaf_rn(aro1, mro1, __fmul_rn(oro1, y1));
        g_partial[dir][row][0] = mro0;
        g_partial[dir][row][1] = mro1;
    }
}

__global__ void fin_kernel(float* __restrict__ out)
{
    const int b = threadIdx.x;
    float v0 = __fadd_rn(g_partial[0][b][0], g_partial[1][b][0]);
    float v1 = __fadd_rn(g_partial[0][b][1], g_partial[1][b][1]);
    // jax.nn.log_softmax: shifted = x - max; out = shifted - log(sum(exp(shifted)))
    float mx = fmaxf(v0, v1);
    float sh0 = __fsub_rn(v0, mx);
    float sh1 = __fsub_rn(v1, mx);
    float e0 = (float)exp((double)sh0);
    float e1 = (float)exp((double)sh1);
    float lse = (float)log((double)__fadd_rn(e0, e1));
    out[2*b + 0] = __fsub_rn(sh0, lse);
    out[2*b + 1] = __fsub_rn(sh1, lse);
}

extern "C" void kernel_launch(void* const* d_in, const int* in_sizes, int n_in,
                              void* d_out, int out_size)
{
    (void)in_sizes; (void)n_in; (void)out_size;
    Params prm;
    for (int i = 0; i < 24; i++) prm.in[i] = (const float*)d_in[i];

    cudaFuncSetAttribute(srnn_kernel,
                         cudaFuncAttributeMaxDynamicSharedMemorySize, SMEM_BYTES);
    srnn_kernel<<<BATCH, NTH, SMEM_BYTES>>>(prm);
    fin_kernel<<<1, BATCH>>>((float*)d_out);
}

// round 10
// speedup vs baseline: 1.3095x; 1.1224x over previous
#include <cuda_runtime.h>
#include <math.h>

#define SEQ   1000
#define HID   100
#define IND   8
#define BATCH 128
#define NOUT  2
#define B_J0  0.01f
#define BETA  1.8f

#define NTH 64   // 2 warps per block, one batch row per warp
#define SMEM_FLOATS (3*HID*HID)   // Wrec1, Wrec2, Win2
#define SMEM_BYTES  (SMEM_FLOATS * 4)

struct Params { const float* in[24]; };

// partial readout accumulators: [dir][batch][out]
__device__ float g_partial[2][BATCH][NOUT];

// XLA:CPU vectorized f32 exp (Cephes / GenerateVF32Exp). Matches reference
// bit-for-bit on this problem's input range (established R5/R6/R8).
__device__ __forceinline__ float xla_expf(float x)
{
    const float exp_hi = 88.3762626647950f;
    const float exp_lo = -88.3762626647949f;
    const float LOG2EF = 1.44269504088896341f;
    const float C1 = 0.693359375f;
    const float C2 = -2.12194440e-4f;
    const float p0 = 1.9875691500E-4f;
    const float p1 = 1.3981999507E-3f;
    const float p2 = 8.3334519073E-3f;
    const float p3 = 4.1665795894E-2f;
    const float p4 = 1.6666665459E-1f;
    const float p5 = 5.0000001201E-1f;

    float xc  = fminf(fmaxf(x, exp_lo), exp_hi);
    float fx  = floorf(__fmaf_rn(xc, LOG2EF, 0.5f));
    float tmp = __fmul_rn(C1, fx);
    float z   = __fmul_rn(C2, fx);
    float r   = __fsub_rn(xc, tmp);
    r = __fsub_rn(r, z);
    z = __fmul_rn(r, r);
    float y = __fmaf_rn(r, p0, p1);
    y = __fmaf_rn(y, r, p2);
    y = __fmaf_rn(y, r, p3);
    y = __fmaf_rn(y, r, p4);
    y = __fmaf_rn(y, r, p5);
    y = __fmaf_rn(y, z, r);
    y = __fadd_rn(y, 1.0f);
    int n = (int)fx;
    float s = __uint_as_float((unsigned)(n + 127) << 23);
    return fmaxf(__fmul_rn(y, s), x);
}

// Sparse gather over one ballot word, unrolled by 2 set bits per iteration.
// Accumulation order per slot is strictly ascending bit index with a single
// accumulator -> bit-identical to the reference serial-k order.
#define GATHER_WORD(mask, smembase, acc)                                   \
    {                                                                      \
        unsigned m_ = (mask);                                              \
        while (m_) {                                                       \
            int b0_ = __ffs(m_) - 1; m_ &= m_ - 1;                         \
            const float* p0_ = (smembase) + b0_*HID;                       \
            if (m_) {                                                      \
                int b1_ = __ffs(m_) - 1; m_ &= m_ - 1;                     \
                const float* p1_ = (smembase) + b1_*HID;                   \
                float t00_=p0_[0], t01_=p0_[32], t02_=p0_[64], t03_=p0_[off3]; \
                float t10_=p1_[0], t11_=p1_[32], t12_=p1_[64], t13_=p1_[off3]; \
                acc[0] = __fadd_rn(__fadd_rn(acc[0], t00_), t10_);         \
                acc[1] = __fadd_rn(__fadd_rn(acc[1], t01_), t11_);         \
                acc[2] = __fadd_rn(__fadd_rn(acc[2], t02_), t12_);         \
                acc[3] = __fadd_rn(__fadd_rn(acc[3], t03_), t13_);         \
            } else {                                                       \
                acc[0] = __fadd_rn(acc[0], p0_[0]);                        \
                acc[1] = __fadd_rn(acc[1], p0_[32]);                       \
                acc[2] = __fadd_rn(acc[2], p0_[64]);                       \
                acc[3] = __fadd_rn(acc[3], p0_[off3]);                     \
            }                                                              \
        }                                                                  \
    }

__global__ void __launch_bounds__(NTH, 1)
srnn_kernel(Params prm)
{
    extern __shared__ float sm[];
    float* sW1 = sm;                    // layer1 Wrec  [100][100]
    float* sW2 = sm + HID*HID;          // layer2 Wrec  [100][100]
    float* sI2 = sm + 2*HID*HID;        // layer2 Win   [100][100]

    const int tid  = threadIdx.x;
    const int lane = tid & 31;
    const int wid  = tid >> 5;                // warp in block = row select
    const int dir  = blockIdx.x & 1;          // 0 = forward, 1 = backward
    const int row  = (blockIdx.x >> 1) * 2 + wid;

    const float* inp = prm.in[0];
    const int b1i = dir ? 6 : 1;    // layer1 param base (fw1 / bw1)
    const int b2i = dir ? 16 : 11;  // layer2 param base (fw2 / bw2)
    const float* Win1  = prm.in[b1i + 0];
    const float* b1v   = prm.in[b1i + 1];
    const float* Wr1   = prm.in[b1i + 2];
    const float* tm1   = prm.in[b1i + 3];
    const float* ta1   = prm.in[b1i + 4];
    const float* Win2g = prm.in[b2i + 0];
    const float* b2vv  = prm.in[b2i + 1];
    const float* Wr2   = prm.in[b2i + 2];
    const float* tm2   = prm.in[b2i + 3];
    const float* ta2   = prm.in[b2i + 4];
    const float* roW   = prm.in[21] + dir * (HID * NOUT);
    const float* rob   = prm.in[22];
    const float* rotau = prm.in[23];

    // ---- stage weights to SMEM (both warps cooperate) ----
    for (int i = tid; i < HID*HID; i += NTH) {
        sW1[i] = Wr1[i];
        sW2[i] = Wr2[i];
        sI2[i] = Win2g[i];
    }

    // ---- per-thread constants / state (4 neuron slots: lane + 32*s) ----
    const bool v3 = (lane < 4);
    int hs[4];
    hs[0] = lane; hs[1] = lane + 32; hs[2] = lane + 64; hs[3] = v3 ? lane + 96 : 0;
    const int off3 = v3 ? 96 : 0;   // safe smem gather offset for slot 3

    float w_in[4][IND];
    float bias1[4], bias2[4];
    float a1[4], om1[4], r1[4], or1[4], a2[4], om2[4], r2[4], or2[4];
    float ro0[4], ro1[4];           // readout weights for owned slots
    #pragma unroll
    for (int s = 0; s < 4; s++) {
        int h = hs[s];
        #pragma unroll
        for (int d = 0; d < IND; d++) w_in[s][d] = Win1[d*HID + h];
        bias1[s] = b1v[h]; bias2[s] = b2vv[h];
        a1[s] = xla_expf(__fdiv_rn(-1.0f, tm1[h])); om1[s] = __fsub_rn(1.0f, a1[s]);
        r1[s] = xla_expf(__fdiv_rn(-1.0f, ta1[h])); or1[s] = __fsub_rn(1.0f, r1[s]);
        a2[s] = xla_expf(__fdiv_rn(-1.0f, tm2[h])); om2[s] = __fsub_rn(1.0f, a2[s]);
        r2[s] = xla_expf(__fdiv_rn(-1.0f, ta2[h])); or2[s] = __fsub_rn(1.0f, r2[s]);
        ro0[s] = roW[h*NOUT + 0];
        ro1[s] = roW[h*NOUT + 1];
    }
    if (!v3) { ro0[3] = 0.f; ro1[3] = 0.f; }
    float mem1[4] = {0.f,0.f,0.f,0.f}, bb1[4] = {B_J0,B_J0,B_J0,B_J0}, s1[4] = {0.f,0.f,0.f,0.f};
    float mem2[4] = {0.f,0.f,0.f,0.f}, bb2[4] = {B_J0,B_J0,B_J0,B_J0}, s2[4] = {0.f,0.f,0.f,0.f};

    // distributed readout state (linear recursion -> per-lane partials are exact
    // up to smooth rounding; spike path unaffected)
    float aro0 = xla_expf(__fdiv_rn(-1.0f, rotau[0])), oro0 = __fsub_rn(1.0f, aro0);
    float aro1 = xla_expf(__fdiv_rn(-1.0f, rotau[1])), oro1 = __fsub_rn(1.0f, aro1);
    float mro0 = 0.f, mro1 = 0.f;
    float rb0 = 0.f, rb1 = 0.f;
    if (lane == 0 && dir == 0) { rb0 = rob[0]; rb1 = rob[1]; }  // counted once

    const float* xrow = inp + (size_t)row * SEQ * IND;

    __syncthreads();   // weights staged (one-time)

    unsigned B1[4] = {0u,0u,0u,0u};   // layer1 spikes, previous step
    unsigned B2[4] = {0u,0u,0u,0u};   // layer2 spikes, previous step

    // prefetch x for t = 0
    float xn[IND];
    {
        const int te = dir ? (SEQ - 1) : 0;
        #pragma unroll
        for (int d = 0; d < IND; d++) xn[d] = __ldg(xrow + te*IND + d);
    }

    for (int t = 0; t < SEQ; t++) {
        float xc[IND];
        #pragma unroll
        for (int d = 0; d < IND; d++) xc[d] = xn[d];
        if (t + 1 < SEQ) {  // prefetch next step's input
            const int te = dir ? (SEQ - 2 - t) : (t + 1);
            #pragma unroll
            for (int d = 0; d < IND; d++) xn[d] = __ldg(xrow + te*IND + d);
        }

        // recurrent gathers from previous-step spikes (ascending j preserved)
        float rec1[4] = {0.f,0.f,0.f,0.f};
        float rec2[4] = {0.f,0.f,0.f,0.f};
        #pragma unroll
        for (int w = 0; w < 4; w++) {
            GATHER_WORD(B1[w], sW1 + w*32*HID + lane, rec1);
        }
        #pragma unroll
        for (int w = 0; w < 4; w++) {
            GATHER_WORD(B2[w], sW2 + w*32*HID + lane, rec2);
        }

        // ---- layer1 update (4 slots) ----
        bool pr1[4];
        #pragma unroll
        for (int s = 0; s < 4; s++) {
            // K=8 input dot, LLVM VF=4 shape: acc_d = fma(x[4+d],w[4+d],x[d]*w[d]);
            // horizontal pairwise: (A0+A1) + (A2+A3)
            float A0 = __fmaf_rn(xc[4], w_in[s][4], __fmul_rn(xc[0], w_in[s][0]));
            float A1 = __fmaf_rn(xc[5], w_in[s][5], __fmul_rn(xc[1], w_in[s][1]));
            float A2 = __fmaf_rn(xc[6], w_in[s][6], __fmul_rn(xc[2], w_in[s][2]));
            float A3 = __fmaf_rn(xc[7], w_in[s][7], __fmul_rn(xc[3], w_in[s][3]));
            float in1 = __fadd_rn(__fadd_rn(A0, A1), __fadd_rn(A2, A3));

            float cur = __fadd_rn(__fadd_rn(in1, bias1[s]), rec1[s]);
            bb1[s] = __fmaf_rn(r1[s], bb1[s], __fmul_rn(or1[s], s1[s]));
            float thr = __fmaf_rn(BETA, bb1[s], B_J0);
            mem1[s] = __fmaf_rn(a1[s], mem1[s], __fmul_rn(om1[s], cur));
            mem1[s] = __fmaf_rn(-thr, s1[s], mem1[s]);
            pr1[s] = __fsub_rn(mem1[s], thr) > 0.f;
            s1[s] = pr1[s] ? 1.f : 0.f;
        }
        if (!v3) { pr1[3] = false; s1[3] = 0.f; }
        unsigned NB1[4];
        NB1[0] = __ballot_sync(0xffffffffu, pr1[0]);
        NB1[1] = __ballot_sync(0xffffffffu, pr1[1]);
        NB1[2] = __ballot_sync(0xffffffffu, pr1[2]);
        NB1[3] = __ballot_sync(0xffffffffu, pr1[3]);

        // ---- layer2 input gather (THIS step's layer1 spikes) ----
        float in2[4] = {0.f,0.f,0.f,0.f};
        #pragma unroll
        for (int w = 0; w < 4; w++) {
            GATHER_WORD(NB1[w], sI2 + w*32*HID + lane, in2);
        }

        // ---- layer2 update (4 slots) ----
        bool pr2[4];
        #pragma unroll
        for (int s = 0; s < 4; s++) {
            float cur = __fadd_rn(__fadd_rn(in2[s], bias2[s]), rec2[s]);
            bb2[s] = __fmaf_rn(r2[s], bb2[s], __fmul_rn(or2[s], s2[s]));
            float thr = __fmaf_rn(BETA, bb2[s], B_J0);
            mem2[s] = __fmaf_rn(a2[s], mem2[s], __fmul_rn(om2[s], cur));
            mem2[s] = __fmaf_rn(-thr, s2[s], mem2[s]);
            pr2[s] = __fsub_rn(mem2[s], thr) > 0.f;
            s2[s] = pr2[s] ? 1.f : 0.f;
        }
        if (!v3) { pr2[3] = false; s2[3] = 0.f; }
        unsigned NB2[4];
        NB2[0] = __ballot_sync(0xffffffffu, pr2[0]);
        NB2[1] = __ballot_sync(0xffffffffu, pr2[1]);
        NB2[2] = __ballot_sync(0xffffffffu, pr2[2]);
        NB2[3] = __ballot_sync(0xffffffffu, pr2[3]);

        // ---- distributed readout of THIS step (smooth path, order-free) ----
        {
            float y0p = __fmaf_rn(s2[0], ro0[0],
                        __fmaf_rn(s2[1], ro0[1],
                        __fmaf_rn(s2[2], ro0[2],
                        __fmaf_rn(s2[3], ro0[3], rb0))));
            float y1p = __fmaf_rn(s2[0], ro1[0],
                        __fmaf_rn(s2[1], ro1[1],
                        __fmaf_rn(s2[2], ro1[2],
                        __fmaf_rn(s2[3], ro1[3], rb1))));
            mro0 = __fmaf_rn(aro0, mro0, __fmul_rn(oro0, y0p));
            mro1 = __fmaf_rn(aro1, mro1, __fmul_rn(oro1, y1p));
        }

        #pragma unroll
        for (int w = 0; w < 4; w++) { B1[w] = NB1[w]; B2[w] = NB2[w]; }
    }

    // warp-reduce the distributed readout partials (smooth, any order)
    #pragma unroll
    for (int o = 16; o > 0; o >>= 1) {
        mro0 += __shfl_xor_sync(0xffffffffu, mro0, o);
        mro1 += __shfl_xor_sync(0xffffffffu, mro1, o);
    }
    if (lane == 0) {
        g_partial[dir][row][0] = mro0;
        g_partial[dir][row][1] = mro1;
    }
}

__global__ void fin_kernel(float* __restrict__ out)
{
    const int b = threadIdx.x;
    float v0 = __fadd_rn(g_partial[0][b][0], g_partial[1][b][0]);
    float v1 = __fadd_rn(g_partial[0][b][1], g_partial[1][b][1]);
    // jax.nn.log_softmax: shifted = x - max; out = shifted - log(sum(exp(shifted)))
    float mx = fmaxf(v0, v1);
    float sh0 = __fsub_rn(v0, mx);
    float sh1 = __fsub_rn(v1, mx);
    float e0 = (float)exp((double)sh0);
    float e1 = (float)exp((double)sh1);
    float lse = (float)log((double)__fadd_rn(e0, e1));
    out[2*b + 0] = __fsub_rn(sh0, lse);
    out[2*b + 1] = __fsub_rn(sh1, lse);
}

extern "C" void kernel_launch(void* const* d_in, const int* in_sizes, int n_in,
                              void* d_out, int out_size)
{
    (void)in_sizes; (void)n_in; (void)out_size;
    Params prm;
    for (int i = 0; i < 24; i++) prm.in[i] = (const float*)d_in[i];

    cudaFuncSetAttribute(srnn_kernel,
                         cudaFuncAttributeMaxDynamicSharedMemorySize, SMEM_BYTES);
    srnn_kernel<<<BATCH, NTH, SMEM_BYTES>>>(prm);
    fin_kernel<<<1, BATCH>>>((float*)d_out);
}